// round 4
// baseline (speedup 1.0000x reference)
#include <cuda_runtime.h>
#include <cuda_bf16.h>

// Problem constants
#define B 8
#define N 2048
#define D 1024
#define G 8
#define CAP 320
#define NTOK (B*N)             // 16384
#define SLAB (G*CAP)           // 2560 floats per token
#define TB 32                  // tokens per gate block
#define NBLK (NTOK/TB)         // 512 blocks
#define ZBLK (NTOK*SLAB/4/NBLK) // 20480 float4 zeroed per block
#define ZPT (ZBLK/256)         // 80 float4 per zero thread

// Scratch (device globals; no allocation allowed)
__device__ int    g_pack[NTOK];   // i1 | i2<<4 | use2<<8
__device__ float2 g_gates[NTOK];  // (g1n, g2n)

// ---------------------------------------------------------------------------
// K1: warp-specialized fused kernel.
//   threads   0-255: gating (register-resident W, k-split, shuffle butterfly)
//   threads 256-511: zero-fill this block's 320KB output slice (80 STG.128
//                    each, fully independent -> store-queue paced, isolated
//                    from the gate warps' critical path)
// ---------------------------------------------------------------------------
__global__ __launch_bounds__(512) void k_gate_zero(const float* __restrict__ x,
                                                   const float* __restrict__ w,
                                                   float* __restrict__ out) {
    __shared__ float part[G * 8 * TB];   // [(e*8+warp)*TB + t], 8 KB

    int tid = threadIdx.x;

    if (tid >= 256) {
        // ---------------- zero-fill role ----------------
        int zt = tid - 256;
        float4* zbase = (float4*)out + (size_t)blockIdx.x * ZBLK + zt;
        const float4 ZV = make_float4(0.f, 0.f, 0.f, 0.f);
#pragma unroll
        for (int j = 0; j < ZPT; j++)
            zbase[j * 256] = ZV;
        __syncthreads();   // match gate-side barrier
        return;
    }

    // ---------------- gating role ----------------
    int warp = tid >> 5, lane = tid & 31;
    int k0 = warp * 128 + lane * 4;      // this thread's 4 k-values (fixed)

    // W coefficients for owned k's -> registers (w is [D, G] row-major)
    float4 wv0 = *(const float4*)(w + k0 * G + 0);
    float4 wv1 = *(const float4*)(w + k0 * G + 4);
    float4 wv2 = *(const float4*)(w + k0 * G + 8);
    float4 wv3 = *(const float4*)(w + k0 * G + 12);
    float4 wv4 = *(const float4*)(w + k0 * G + 16);
    float4 wv5 = *(const float4*)(w + k0 * G + 20);
    float4 wv6 = *(const float4*)(w + k0 * G + 24);
    float4 wv7 = *(const float4*)(w + k0 * G + 28);
    float wreg[G][4];
    wreg[0][0]=wv0.x; wreg[1][0]=wv0.y; wreg[2][0]=wv0.z; wreg[3][0]=wv0.w;
    wreg[4][0]=wv1.x; wreg[5][0]=wv1.y; wreg[6][0]=wv1.z; wreg[7][0]=wv1.w;
    wreg[0][1]=wv2.x; wreg[1][1]=wv2.y; wreg[2][1]=wv2.z; wreg[3][1]=wv2.w;
    wreg[4][1]=wv3.x; wreg[5][1]=wv3.y; wreg[6][1]=wv3.z; wreg[7][1]=wv3.w;
    wreg[0][2]=wv4.x; wreg[1][2]=wv4.y; wreg[2][2]=wv4.z; wreg[3][2]=wv4.w;
    wreg[4][2]=wv5.x; wreg[5][2]=wv5.y; wreg[6][2]=wv5.z; wreg[7][2]=wv5.w;
    wreg[0][3]=wv6.x; wreg[1][3]=wv6.y; wreg[2][3]=wv6.z; wreg[3][3]=wv6.w;
    wreg[4][3]=wv7.x; wreg[5][3]=wv7.y; wreg[6][3]=wv7.z; wreg[7][3]=wv7.w;

    int tok0 = blockIdx.x * TB;
    const unsigned FULL = 0xffffffffu;

    int bit0 = lane & 1;
    int my_e = (lane & 1) * 4 + (lane & 2) + ((lane >> 2) & 1);

#pragma unroll 4
    for (int t = 0; t < TB; t++) {
        const float4 xv = *(const float4*)(x + (size_t)(tok0 + t) * D + k0);

        float acc[G];
#pragma unroll
        for (int e = 0; e < G; e++) {
            acc[e] = fmaf(xv.x, wreg[e][0],
                     fmaf(xv.y, wreg[e][1],
                     fmaf(xv.z, wreg[e][2],
                          xv.w * wreg[e][3])));
        }

        // Stage A (xor 1): 8 -> 4
        float a0 = (bit0 ? acc[4] : acc[0]) + __shfl_xor_sync(FULL, bit0 ? acc[0] : acc[4], 1);
        float a1 = (bit0 ? acc[5] : acc[1]) + __shfl_xor_sync(FULL, bit0 ? acc[1] : acc[5], 1);
        float a2 = (bit0 ? acc[6] : acc[2]) + __shfl_xor_sync(FULL, bit0 ? acc[2] : acc[6], 1);
        float a3 = (bit0 ? acc[7] : acc[3]) + __shfl_xor_sync(FULL, bit0 ? acc[3] : acc[7], 1);
        // Stage B (xor 2): 4 -> 2
        int bit1 = (lane >> 1) & 1;
        float b0 = (bit1 ? a2 : a0) + __shfl_xor_sync(FULL, bit1 ? a0 : a2, 2);
        float b1 = (bit1 ? a3 : a1) + __shfl_xor_sync(FULL, bit1 ? a1 : a3, 2);
        // Stage C (xor 4): 2 -> 1
        int bit2 = (lane >> 2) & 1;
        float c = (bit2 ? b1 : b0) + __shfl_xor_sync(FULL, bit2 ? b0 : b1, 4);
        // Stage D: combine lane groups (same expert)
        c += __shfl_xor_sync(FULL, c, 8);
        c += __shfl_xor_sync(FULL, c, 16);

        if (lane < 8)
            part[(my_e * 8 + warp) * TB + t] = c;
    }
    __syncthreads();

    // Finalize: one thread per token
    if (tid < TB) {
        int t = tid;
        float p[G];
#pragma unroll
        for (int e = 0; e < G; e++) {
            float s = 0.f;
#pragma unroll
            for (int wq = 0; wq < 8; wq++) s += part[(e * 8 + wq) * TB + t];
            p[e] = s;
        }
        float m = p[0];
#pragma unroll
        for (int e = 1; e < G; e++) m = fmaxf(m, p[e]);
        float s = 0.f;
#pragma unroll
        for (int e = 0; e < G; e++) { p[e] = expf(p[e] - m); s += p[e]; }
        float inv = 1.f / s;
#pragma unroll
        for (int e = 0; e < G; e++) p[e] *= inv;

        int i1 = 0; float g1 = p[0];
#pragma unroll
        for (int e = 1; e < G; e++) if (p[e] > g1) { g1 = p[e]; i1 = e; }
        int i2 = 0; float g2 = -1.f;
#pragma unroll
        for (int e = 0; e < G; e++)
            if (e != i1 && p[e] > g2) { g2 = p[e]; i2 = e; }

        float g1n = g1 / (g1 + g2 + 1e-9f);
        float g2n = g2 / (g1n + g2 + 1e-9f);
        int use2 = (g2n > 0.2f) ? 1 : 0;

        int tok = tok0 + t;
        g_pack[tok] = i1 | (i2 << 4) | (use2 << 8);
        g_gates[tok] = make_float2(g1n, g2n);
    }
}

// ---------------------------------------------------------------------------
// K2: per-batch token scan + scatter. 1 block per batch, 256 threads x 8
// tokens each. 8 expert counters packed as 2 x u64 (16 bits/expert).
// Final offsets are scattered directly into the (already-zeroed) output.
// ---------------------------------------------------------------------------
__global__ __launch_bounds__(256) void k_scan_scatter(float* __restrict__ out) {
    __shared__ unsigned long long sl[256], sh[256];
    __shared__ int count1[G];

    int b = blockIdx.x, tid = threadIdx.x;
    int base = b * N + tid * 8;

    int pk[8];
#pragma unroll
    for (int j = 0; j < 8; j++) pk[j] = g_pack[base + j];

    // ---- pass 1: top-1 positions ----
    unsigned long long lo = 0, hi = 0;
#pragma unroll
    for (int j = 0; j < 8; j++) {
        int i1 = pk[j] & 15;
        if (i1 < 4) lo += 1ULL << (i1 * 16); else hi += 1ULL << ((i1 - 4) * 16);
    }
    unsigned long long mylo = lo, myhi = hi;
    sl[tid] = lo; sh[tid] = hi;
    __syncthreads();
    for (int o = 1; o < 256; o <<= 1) {
        unsigned long long a = 0, c = 0;
        if (tid >= o) { a = sl[tid - o]; c = sh[tid - o]; }
        __syncthreads();
        if (tid >= o) { sl[tid] += a; sh[tid] += c; }
        __syncthreads();
    }
    unsigned long long exlo = sl[tid] - mylo, exhi = sh[tid] - myhi;
    if (tid == 255) {
#pragma unroll
        for (int e = 0; e < 4; e++) {
            count1[e]     = min((int)((sl[255] >> (e * 16)) & 0xFFFF), CAP);
            count1[e + 4] = min((int)((sh[255] >> (e * 16)) & 0xFFFF), CAP);
        }
    }
    int pos1[8];
    {
        unsigned long long rlo = exlo, rhi = exhi;
#pragma unroll
        for (int j = 0; j < 8; j++) {
            int i1 = pk[j] & 15;
            int p = (i1 < 4) ? (int)((rlo >> (i1 * 16)) & 0xFFFF)
                             : (int)((rhi >> ((i1 - 4) * 16)) & 0xFFFF);
            pos1[j] = p;
            if (i1 < 4) rlo += 1ULL << (i1 * 16); else rhi += 1ULL << ((i1 - 4) * 16);
        }
    }
    __syncthreads();  // protect sl/sh + count1 before reuse

    // ---- pass 2: top-2 positions (only thresholded tokens count) ----
    lo = 0; hi = 0;
#pragma unroll
    for (int j = 0; j < 8; j++) {
        if (pk[j] >> 8) {
            int i2 = (pk[j] >> 4) & 15;
            if (i2 < 4) lo += 1ULL << (i2 * 16); else hi += 1ULL << ((i2 - 4) * 16);
        }
    }
    mylo = lo; myhi = hi;
    sl[tid] = lo; sh[tid] = hi;
    __syncthreads();
    for (int o = 1; o < 256; o <<= 1) {
        unsigned long long a = 0, c = 0;
        if (tid >= o) { a = sl[tid - o]; c = sh[tid - o]; }
        __syncthreads();
        if (tid >= o) { sl[tid] += a; sh[tid] += c; }
        __syncthreads();
    }
    exlo = sl[tid] - mylo; exhi = sh[tid] - myhi;

    unsigned long long rlo = exlo, rhi = exhi;
#pragma unroll
    for (int j = 0; j < 8; j++) {
        int t = base + j;
        int i1 = pk[j] & 15, i2 = (pk[j] >> 4) & 15, use2 = pk[j] >> 8;
        float2 g = g_gates[t];
        float* o = out + (size_t)t * SLAB;
        if (pos1[j] < CAP) o[i1 * CAP + pos1[j]] = g.x;
        if (use2) {
            int p = (i2 < 4) ? (int)((rlo >> (i2 * 16)) & 0xFFFF)
                             : (int)((rhi >> ((i2 - 4) * 16)) & 0xFFFF);
            int pos2 = count1[i2] + p;
            if (pos2 < CAP) o[i2 * CAP + pos2] = g.y;
            if (i2 < 4) rlo += 1ULL << (i2 * 16); else rhi += 1ULL << ((i2 - 4) * 16);
        }
    }
}

extern "C" void kernel_launch(void* const* d_in, const int* in_sizes, int n_in,
                              void* d_out, int out_size) {
    const float* x = (const float*)d_in[0];
    const float* w = (const float*)d_in[1];
    float* out = (float*)d_out;

    k_gate_zero<<<NBLK, 512>>>(x, w, out);
    k_scan_scatter<<<B, 256>>>(out);
}

// round 5
// speedup vs baseline: 1.2410x; 1.2410x over previous
#include <cuda_runtime.h>
#include <cuda_bf16.h>

// Problem constants
#define B 8
#define N 2048
#define D 1024
#define G 8
#define CAP 320
#define NTOK (B*N)              // 16384
#define SLAB (G*CAP)            // 2560 floats per token
#define TB 32                   // tokens per gate block
#define NGATE (NTOK/TB)         // 512 gate blocks
#define NZERO 1024              // zero blocks
#define TOTAL_F4 (NTOK*SLAB/4)  // 10485760
#define ZBLK (TOTAL_F4/NZERO)   // 10240 float4 per zero block
#define ZPT (ZBLK/256)          // 40 float4 per zero thread

// Scratch (device globals; no allocation allowed)
__device__ int    g_pack[NTOK];   // i1 | i2<<4 | use2<<8
__device__ float2 g_gates[NTOK];  // (g1n, g2n)

// ---------------------------------------------------------------------------
// K1: block-role-specialized fused kernel. 1536 blocks of 256 threads.
//   blockIdx % 3 == 0  -> gate block (gid = blockIdx/3, 512 of them)
//   else               -> zero block (zid = (blockIdx/3)*2 + mod-1, 1024)
// Roles are interleaved so every scheduling wave carries a ~1:2 gate:zero mix;
// zero blocks saturate DRAM writes while gate blocks use the issue slots.
// No intra-block coupling between roles (the R4 failure mode).
// ---------------------------------------------------------------------------
__global__ __launch_bounds__(256) void k_fused(const float* __restrict__ x,
                                               const float* __restrict__ w,
                                               float* __restrict__ out) {
    int bid = blockIdx.x;
    int mod = bid % 3;
    int tid = threadIdx.x;

    if (mod != 0) {
        // ---------------- zero role ----------------
        int zid = (bid / 3) * 2 + (mod - 1);          // 0..1023
        float4* zbase = (float4*)out + (size_t)zid * ZBLK + tid;
        const float4 ZV = make_float4(0.f, 0.f, 0.f, 0.f);
#pragma unroll
        for (int j = 0; j < ZPT; j++)
            zbase[j * 256] = ZV;
        return;
    }

    // ---------------- gate role (proven R2 kernel) ----------------
    __shared__ float part[G * 8 * TB];   // [(e*8+warp)*TB + t], 8 KB

    int warp = tid >> 5, lane = tid & 31;
    int k0 = warp * 128 + lane * 4;

    // W coefficients for owned k's -> registers (w is [D, G] row-major)
    float4 wv0 = *(const float4*)(w + k0 * G + 0);
    float4 wv1 = *(const float4*)(w + k0 * G + 4);
    float4 wv2 = *(const float4*)(w + k0 * G + 8);
    float4 wv3 = *(const float4*)(w + k0 * G + 12);
    float4 wv4 = *(const float4*)(w + k0 * G + 16);
    float4 wv5 = *(const float4*)(w + k0 * G + 20);
    float4 wv6 = *(const float4*)(w + k0 * G + 24);
    float4 wv7 = *(const float4*)(w + k0 * G + 28);
    float wreg[G][4];
    wreg[0][0]=wv0.x; wreg[1][0]=wv0.y; wreg[2][0]=wv0.z; wreg[3][0]=wv0.w;
    wreg[4][0]=wv1.x; wreg[5][0]=wv1.y; wreg[6][0]=wv1.z; wreg[7][0]=wv1.w;
    wreg[0][1]=wv2.x; wreg[1][1]=wv2.y; wreg[2][1]=wv2.z; wreg[3][1]=wv2.w;
    wreg[4][1]=wv3.x; wreg[5][1]=wv3.y; wreg[6][1]=wv3.z; wreg[7][1]=wv3.w;
    wreg[0][2]=wv4.x; wreg[1][2]=wv4.y; wreg[2][2]=wv4.z; wreg[3][2]=wv4.w;
    wreg[4][2]=wv5.x; wreg[5][2]=wv5.y; wreg[6][2]=wv5.z; wreg[7][2]=wv5.w;
    wreg[0][3]=wv6.x; wreg[1][3]=wv6.y; wreg[2][3]=wv6.z; wreg[3][3]=wv6.w;
    wreg[4][3]=wv7.x; wreg[5][3]=wv7.y; wreg[6][3]=wv7.z; wreg[7][3]=wv7.w;

    int tok0 = (bid / 3) * TB;
    const unsigned FULL = 0xffffffffu;

    int bit0 = lane & 1;
    int my_e = (lane & 1) * 4 + (lane & 2) + ((lane >> 2) & 1);

#pragma unroll 4
    for (int t = 0; t < TB; t++) {
        const float4 xv = *(const float4*)(x + (size_t)(tok0 + t) * D + k0);

        float acc[G];
#pragma unroll
        for (int e = 0; e < G; e++) {
            acc[e] = fmaf(xv.x, wreg[e][0],
                     fmaf(xv.y, wreg[e][1],
                     fmaf(xv.z, wreg[e][2],
                          xv.w * wreg[e][3])));
        }

        float a0 = (bit0 ? acc[4] : acc[0]) + __shfl_xor_sync(FULL, bit0 ? acc[0] : acc[4], 1);
        float a1 = (bit0 ? acc[5] : acc[1]) + __shfl_xor_sync(FULL, bit0 ? acc[1] : acc[5], 1);
        float a2 = (bit0 ? acc[6] : acc[2]) + __shfl_xor_sync(FULL, bit0 ? acc[2] : acc[6], 1);
        float a3 = (bit0 ? acc[7] : acc[3]) + __shfl_xor_sync(FULL, bit0 ? acc[3] : acc[7], 1);
        int bit1 = (lane >> 1) & 1;
        float b0 = (bit1 ? a2 : a0) + __shfl_xor_sync(FULL, bit1 ? a0 : a2, 2);
        float b1 = (bit1 ? a3 : a1) + __shfl_xor_sync(FULL, bit1 ? a1 : a3, 2);
        int bit2 = (lane >> 2) & 1;
        float c = (bit2 ? b1 : b0) + __shfl_xor_sync(FULL, bit2 ? b0 : b1, 4);
        c += __shfl_xor_sync(FULL, c, 8);
        c += __shfl_xor_sync(FULL, c, 16);

        if (lane < 8)
            part[(my_e * 8 + warp) * TB + t] = c;
    }
    __syncthreads();

    if (tid < TB) {
        int t = tid;
        float p[G];
#pragma unroll
        for (int e = 0; e < G; e++) {
            float s = 0.f;
#pragma unroll
            for (int wq = 0; wq < 8; wq++) s += part[(e * 8 + wq) * TB + t];
            p[e] = s;
        }
        float m = p[0];
#pragma unroll
        for (int e = 1; e < G; e++) m = fmaxf(m, p[e]);
        float s = 0.f;
#pragma unroll
        for (int e = 0; e < G; e++) { p[e] = expf(p[e] - m); s += p[e]; }
        float inv = 1.f / s;
#pragma unroll
        for (int e = 0; e < G; e++) p[e] *= inv;

        int i1 = 0; float g1 = p[0];
#pragma unroll
        for (int e = 1; e < G; e++) if (p[e] > g1) { g1 = p[e]; i1 = e; }
        int i2 = 0; float g2 = -1.f;
#pragma unroll
        for (int e = 0; e < G; e++)
            if (e != i1 && p[e] > g2) { g2 = p[e]; i2 = e; }

        float g1n = g1 / (g1 + g2 + 1e-9f);
        float g2n = g2 / (g1n + g2 + 1e-9f);
        int use2 = (g2n > 0.2f) ? 1 : 0;

        int tok = tok0 + t;
        g_pack[tok] = i1 | (i2 << 4) | (use2 << 8);
        g_gates[tok] = make_float2(g1n, g2n);
    }
}

// ---------------------------------------------------------------------------
// K2: scan + scatter, warp-shuffle scans (2 barriers per pass instead of 16).
// 1 block per batch; thread owns 8 consecutive tokens; counters packed as
// 2 x u64 (16 bits per expert).
// ---------------------------------------------------------------------------
__global__ __launch_bounds__(256) void k_scan_scatter(float* __restrict__ out) {
    __shared__ unsigned long long wlo[8], whi[8];
    __shared__ int count1[G];

    int b = blockIdx.x, tid = threadIdx.x;
    int warp = tid >> 5, lane = tid & 31;
    int base = b * N + tid * 8;
    const unsigned FULL = 0xffffffffu;

    int pk[8];
#pragma unroll
    for (int j = 0; j < 8; j++) pk[j] = g_pack[base + j];

    // ================= pass 1: top-1 =================
    unsigned long long lo = 0, hi = 0;
#pragma unroll
    for (int j = 0; j < 8; j++) {
        int i1 = pk[j] & 15;
        if (i1 < 4) lo += 1ULL << (i1 * 16); else hi += 1ULL << ((i1 - 4) * 16);
    }
    // warp-inclusive scan
    unsigned long long slo = lo, shi = hi;
#pragma unroll
    for (int o = 1; o < 32; o <<= 1) {
        unsigned long long t1 = __shfl_up_sync(FULL, slo, o);
        unsigned long long t2 = __shfl_up_sync(FULL, shi, o);
        if (lane >= o) { slo += t1; shi += t2; }
    }
    if (lane == 31) { wlo[warp] = slo; whi[warp] = shi; }
    __syncthreads();
    unsigned long long plo = 0, phi = 0, tlo = 0, thi = 0;
#pragma unroll
    for (int ww = 0; ww < 8; ww++) {
        unsigned long long a = wlo[ww], c = whi[ww];
        if (ww < warp) { plo += a; phi += c; }
        tlo += a; thi += c;
    }
    unsigned long long exlo = plo + slo - lo;   // exclusive prefix for this thread
    unsigned long long exhi = phi + shi - hi;
#pragma unroll
    for (int e = 0; e < 4; e++) {
        count1[e]     = min((int)((tlo >> (e * 16)) & 0xFFFF), CAP);
        count1[e + 4] = min((int)((thi >> (e * 16)) & 0xFFFF), CAP);
    }
    int pos1[8];
    {
        unsigned long long rlo = exlo, rhi = exhi;
#pragma unroll
        for (int j = 0; j < 8; j++) {
            int i1 = pk[j] & 15;
            pos1[j] = (i1 < 4) ? (int)((rlo >> (i1 * 16)) & 0xFFFF)
                               : (int)((rhi >> ((i1 - 4) * 16)) & 0xFFFF);
            if (i1 < 4) rlo += 1ULL << (i1 * 16); else rhi += 1ULL << ((i1 - 4) * 16);
        }
    }
    __syncthreads();   // wlo/whi reuse

    // ================= pass 2: top-2 =================
    lo = 0; hi = 0;
#pragma unroll
    for (int j = 0; j < 8; j++) {
        if (pk[j] >> 8) {
            int i2 = (pk[j] >> 4) & 15;
            if (i2 < 4) lo += 1ULL << (i2 * 16); else hi += 1ULL << ((i2 - 4) * 16);
        }
    }
    slo = lo; shi = hi;
#pragma unroll
    for (int o = 1; o < 32; o <<= 1) {
        unsigned long long t1 = __shfl_up_sync(FULL, slo, o);
        unsigned long long t2 = __shfl_up_sync(FULL, shi, o);
        if (lane >= o) { slo += t1; shi += t2; }
    }
    if (lane == 31) { wlo[warp] = slo; whi[warp] = shi; }
    __syncthreads();
    plo = 0; phi = 0;
#pragma unroll
    for (int ww = 0; ww < 8; ww++) {
        if (ww < warp) { plo += wlo[ww]; phi += whi[ww]; }
    }
    exlo = plo + slo - lo;
    exhi = phi + shi - hi;

    unsigned long long rlo = exlo, rhi = exhi;
#pragma unroll
    for (int j = 0; j < 8; j++) {
        int t = base + j;
        int i1 = pk[j] & 15, i2 = (pk[j] >> 4) & 15, use2 = pk[j] >> 8;
        float2 g = g_gates[t];
        float* o = out + (size_t)t * SLAB;
        if (pos1[j] < CAP) o[i1 * CAP + pos1[j]] = g.x;
        if (use2) {
            int p = (i2 < 4) ? (int)((rlo >> (i2 * 16)) & 0xFFFF)
                             : (int)((rhi >> ((i2 - 4) * 16)) & 0xFFFF);
            int pos2 = count1[i2] + p;
            if (pos2 < CAP) o[i2 * CAP + pos2] = g.y;
            if (i2 < 4) rlo += 1ULL << (i2 * 16); else rhi += 1ULL << ((i2 - 4) * 16);
        }
    }
}

extern "C" void kernel_launch(void* const* d_in, const int* in_sizes, int n_in,
                              void* d_out, int out_size) {
    const float* x = (const float*)d_in[0];
    const float* w = (const float*)d_in[1];
    float* out = (float*)d_out;

    k_fused<<<NGATE + NZERO, 256>>>(x, w, out);
    k_scan_scatter<<<B, 256>>>(out);
}